// round 17
// baseline (speedup 1.0000x reference)
#include <cuda_runtime.h>
#include <cuda_bf16.h>
#include <cstdint>

#define BB 8
#define CC 2048
#define FIN 128
#define FF 64
#define NROWS (BB*CC)
#define LOG2E 1.4426950408889634f

// Scratch (__device__ globals: allocation-free rule)
// g_WhP: 4-pack layout, per 64-row group (= global row>>6), 4096 floats:
//   [grp64*4096 + kt*128 + c*4 + e],  kt=(q>>3)*4+(q&3) for row q (pairs q,q+4),
//   c = col&31, e: 0=(q,c) 1=(q+4,c) 2=(q,c+32) 3=(q+4,c+32).  tf32-rounded.
__device__ float g_WhP[(size_t)NROWS * FF];
__device__ float g_s1[NROWS];                 // s1 * log2e
__device__ float g_s2[NROWS];                 // s2 * log2e
__device__ float g_part[512][64][72];         // per (tile,half): unnorm acc + l at col 64
__device__ float g_partm[512][64];            // per (tile,half): running row max (exp2 dom)

__device__ __forceinline__ float f2tf32f(float x) {
    uint32_t r;
    asm("cvt.rna.tf32.f32 %0, %1;" : "=r"(r) : "f"(x));
    return __uint_as_float(r);
}
__device__ __forceinline__ float ex2f(float x) {
    float r;
    asm("ex2.approx.f32 %0, %1;" : "=f"(r) : "f"(x));
    return r;
}
__device__ __forceinline__ void mma_tf32(float* c,
                                         uint32_t a0, uint32_t a1, uint32_t a2, uint32_t a3,
                                         uint32_t b0, uint32_t b1) {
    asm volatile(
        "mma.sync.aligned.m16n8k8.row.col.f32.tf32.tf32.f32 "
        "{%0,%1,%2,%3}, {%4,%5,%6,%7}, {%8,%9}, {%0,%1,%2,%3};"
        : "+f"(c[0]), "+f"(c[1]), "+f"(c[2]), "+f"(c[3])
        : "r"(a0), "r"(a1), "r"(a2), "r"(a3), "r"(b0), "r"(b1));
}

// ---------------------------------------------------------------------------
// Kernel 1 (R16 verbatim): Wh = H @ W via tf32 MMA; s1,s2 in FULL fp32
// via s = H · (W·a) on raw H/W (accuracy-critical).
// ---------------------------------------------------------------------------
#define KWH_SMEM 68096

__global__ __launch_bounds__(128) void k_wh(const float* __restrict__ H,
                                            const float* __restrict__ W,
                                            const float* __restrict__ a)
{
    extern __shared__ float sm[];
    float*  Wp  = sm;                         // 8192 floats (4-pack of tf32 W)
    float*  Hs  = sm + 8192;                  // 64 x 132 raw fp32 H
    float*  WhS = sm + 8192;                  // alias (64 x 68), used after MMA
    float*  aS  = sm + 8192 + 8448;           // 128
    float2* waS = (float2*)(sm + 8192 + 8448 + 128);  // 128 x {wa1,wa2}*log2e

    int t = threadIdx.x;
    int lane = t & 31, warp = t >> 5;
    int g = lane >> 2, tg = lane & 3;
    int W0 = warp * 16;
    int r0 = blockIdx.x * 64;

    aS[t] = a[t];
    {
        const float4* src = (const float4*)(H + (size_t)r0 * FIN);
#pragma unroll
        for (int p = 0; p < 16; p++) {
            int idx = t + p * 128;
            int r = idx >> 5, c4 = idx & 31;
            *(float4*)&Hs[r * 132 + c4 * 4] = src[idx];
        }
    }
    __syncthreads();

    {
        int k = t;
        const float4* wrow = (const float4*)(W + k * FF);
        float wa1 = 0.f, wa2 = 0.f;
        int ktb = (k >> 3) * 512 + (k & 3) * 128;
        int e0  = (k >> 2) & 1;
#pragma unroll
        for (int i = 0; i < 16; i++) {
            int c4 = (i + (k & 15)) & 15;
            float4 wv = wrow[c4];
#pragma unroll
            for (int j = 0; j < 4; j++) {
                int c = c4 * 4 + j;
                float w = (j == 0) ? wv.x : (j == 1) ? wv.y : (j == 2) ? wv.z : wv.w;
                wa1 = fmaf(w, aS[c], wa1);
                wa2 = fmaf(w, aS[64 + c], wa2);
                Wp[ktb + (c & 31) * 4 + e0 + 2 * (c >> 5)] = f2tf32f(w);
            }
        }
        waS[k] = make_float2(wa1 * LOG2E, wa2 * LOG2E);
    }
    __syncthreads();

    {
        int r = t >> 1, half = t & 1;
        const float*  hrow = &Hs[r * 132 + half * 64];
        const float2* wv   = waS + half * 64;
        float p1 = 0.f, p2 = 0.f;
#pragma unroll
        for (int k = 0; k < 64; k++) {
            float h = hrow[k];
            float2 w2 = wv[k];
            p1 = fmaf(h, w2.x, p1);
            p2 = fmaf(h, w2.y, p2);
        }
        p1 += __shfl_xor_sync(0xffffffffu, p1, 1);
        p2 += __shfl_xor_sync(0xffffffffu, p2, 1);
        if (half == 0) { g_s1[r0 + r] = p1; g_s2[r0 + r] = p2; }
    }

    float4 acc[8];
#pragma unroll
    for (int nf = 0; nf < 8; nf++) acc[nf] = make_float4(0.f, 0.f, 0.f, 0.f);

#pragma unroll
    for (int s = 0; s < 16; s++) {
        int k0 = s * 8;
        uint32_t a0 = __float_as_uint(Hs[(W0 + g) * 132 + k0 + tg]);
        uint32_t a1 = __float_as_uint(Hs[(W0 + g + 8) * 132 + k0 + tg]);
        uint32_t a2 = __float_as_uint(Hs[(W0 + g) * 132 + k0 + tg + 4]);
        uint32_t a3 = __float_as_uint(Hs[(W0 + g + 8) * 132 + k0 + tg + 4]);
        const float* wk = Wp + s * 512 + tg * 128 + g * 4;
#pragma unroll
        for (int nf = 0; nf < 4; nf++) {
            float4 wp = *(const float4*)(wk + nf * 32);
            mma_tf32((float*)&acc[nf],     a0, a1, a2, a3,
                     __float_as_uint(wp.x), __float_as_uint(wp.y));
            mma_tf32((float*)&acc[nf + 4], a0, a1, a2, a3,
                     __float_as_uint(wp.z), __float_as_uint(wp.w));
        }
    }
    __syncthreads();

    {
        int rA = W0 + g;
#pragma unroll
        for (int nf = 0; nf < 8; nf++) {
            int col = (nf < 4) ? (nf * 8 + 2 * tg) : (32 + (nf - 4) * 8 + 2 * tg);
            *(float2*)&WhS[rA * 68 + col]       = make_float2(acc[nf].x, acc[nf].y);
            *(float2*)&WhS[(rA + 8) * 68 + col] = make_float2(acc[nf].z, acc[nf].w);
        }
    }
    __syncthreads();

    {
        float* dst = g_WhP + (size_t)blockIdx.x * 4096;
#pragma unroll
        for (int p = 0; p < 8; p++) {
            int f = t + p * 128;
            int kt = f >> 5, cl = f & 31;
            int q = ((kt >> 2) << 3) + (kt & 3);
            float4 v;
            v.x = f2tf32f(WhS[q * 68 + cl]);
            v.y = f2tf32f(WhS[(q + 4) * 68 + cl]);
            v.z = f2tf32f(WhS[q * 68 + cl + 32]);
            v.w = f2tf32f(WhS[(q + 4) * 68 + cl + 32]);
            *(float4*)(dst + f * 4) = v;
        }
    }
}

// ---------------------------------------------------------------------------
// k_out: SINGLE-PASS online-softmax @ Wh with cp.async DOUBLE-BUFFERED A.
// Grid 512, 2 blocks/SM. A chunk o+1 streams into smem during compress+MMA
// of chunk o; compress reads A from smem (no LDG latency exposure).
// Commit order per iter: [Wh o], [A o+1]; wait_group 2 -> A o resident,
// wait_group 1 -> Wh o resident.
// ---------------------------------------------------------------------------
// dynamic smem (bytes):
//   maskC : uint32[64][8]       @ 0      (2048)
//   s2S   : float [1024]        @ 2048   (4096)
//   s2pair: float2[512]         @ 6144   (4096)
//   whsP  : float [2][4352]     @ 10240  (34816)  (aliased as accS at end)
//   s1s   : float [64]          @ 45056  (256)
//   msS   : float [64]          @ 45312  (256)
//   fsS   : float [64]          @ 45568  (256)
//   bufA  : int [2][64][128]    @ 45824  (65536)
#define KOUT_SMEM 111360

__global__ __launch_bounds__(256, 2) void k_out(const int* __restrict__ A)
{
    extern __shared__ char smemraw[];
    uint32_t (*maskC)[8] = (uint32_t(*)[8])smemraw;
    float*  s2S    = (float*)(smemraw + 2048);
    float2* s2pair = (float2*)(smemraw + 6144);
    float*  whsP   = (float*)(smemraw + 10240);
    float*  s1s    = (float*)(smemraw + 45056);
    float*  msS    = (float*)(smemraw + 45312);
    float*  fsS    = (float*)(smemraw + 45568);
    int*    bufA   = (int*)(smemraw + 45824);

    int t = threadIdx.x;
    int lane = t & 31;
    int warp = t >> 5;
    int grp  = t >> 7;
    int lt   = t & 127;
    int wg   = warp & 3;
    int g = lane >> 2, tg = lane & 3;
    int m0 = wg * 16;

    int bid  = blockIdx.x;
    int half = bid & 1;
    int tile = bid >> 1;
    int b  = tile >> 5;
    int i0 = (tile & 31) << 6;
    int J0 = half << 10;
    const int* Ab = A + (size_t)b * CC * CC;

    uint32_t whs_sb  = (uint32_t)__cvta_generic_to_shared(whsP);
    uint32_t bufA_sb = (uint32_t)__cvta_generic_to_shared(bufA);

    // prologue: start A chunk 0 stream immediately
    {
        int r = t >> 3, c4 = (t & 7) * 4;          // warp covers 4 rows... (coalesced 16B)
        // 2048 int4 total; thread does 8: idx = t + p*256 -> r=idx>>5, c4=idx&31
#pragma unroll
        for (int p = 0; p < 8; p++) {
            int idx = t + p * 256;
            int rr = idx >> 5, cc = idx & 31;
            uint32_t daddr = bufA_sb + (uint32_t)(rr * 128 + cc * 4) * 4u;
            asm volatile("cp.async.cg.shared.global [%0], [%1], 16;"
                         :: "r"(daddr), "l"(Ab + (size_t)(i0 + rr) * CC + J0 + cc * 4));
        }
        asm volatile("cp.async.commit_group;");
        (void)r; (void)c4;
    }

    if (t < 64) {
        s1s[t] = g_s1[b * CC + i0 + t];
        msS[t] = -3.0e38f;
    }
    for (int q = t; q < 1024; q += 256) s2S[q] = g_s2[b * CC + J0 + q];
    __syncthreads();
#pragma unroll
    for (int p = 0; p < 2; p++) {
        int idx = t + p * 256;
        int gj = idx >> 2, tgq = idx & 3;
        s2pair[idx] = make_float2(s2S[gj * 8 + tgq], s2S[gj * 8 + tgq + 4]);
    }

    float4 acc[8];
#pragma unroll
    for (int nf = 0; nf < 8; nf++) acc[nf] = make_float4(0.f, 0.f, 0.f, 0.f);
    float lA = 0.f, lB = 0.f;

    int gbase = (b * 32) + (J0 >> 6);
    int myrowA = m0 + g, myrowB = m0 + g + 8;

    for (int o = 0; o < 8; o++) {
        __syncthreads();                     // prev MMA done: whsP/maskC/fsS reusable

        // -- issue Wh tile o staging (group: Wh o) --
        {
            const float4* src = (const float4*)(g_WhP + (size_t)(gbase + o * 2) * 4096);
#pragma unroll
            for (int p = 0; p < 8; p++) {
                int idx = t + p * 256;
                int gs = idx >> 10, rest = idx & 1023;
                int kt = rest >> 5, f4i = rest & 31;
                uint32_t daddr = whs_sb + (uint32_t)(gs * 4352 + kt * 136 + f4i * 4) * 4u;
                asm volatile("cp.async.cg.shared.global [%0], [%1], 16;"
                             :: "r"(daddr), "l"(src + idx));
            }
            asm volatile("cp.async.commit_group;");
        }

        // -- issue A chunk o+1 prefetch (group: A o+1); o=7 -> dummy re-read of chunk 0 --
        {
            int oc = (o + 1) & 7;
            int Jc = J0 + oc * 128;
            uint32_t bb = (uint32_t)(((o + 1) & 1) * 8192);
#pragma unroll
            for (int p = 0; p < 8; p++) {
                int idx = t + p * 256;
                int rr = idx >> 5, cc = idx & 31;
                uint32_t daddr = bufA_sb + (bb + (uint32_t)(rr * 128 + cc * 4)) * 4u;
                asm volatile("cp.async.cg.shared.global [%0], [%1], 16;"
                             :: "r"(daddr), "l"(Ab + (size_t)(i0 + rr) * CC + Jc + cc * 4));
            }
            asm volatile("cp.async.commit_group;");
        }

        asm volatile("cp.async.wait_group 2;" ::: "memory");   // A chunk o resident
        __syncthreads();

        // -- compress chunk o from smem: 8 rows/warp --
        {
            const int* bufc = bufA + (o & 1) * 8192;
#pragma unroll
            for (int rr = 0; rr < 8; rr++) {
                int rowl = warp * 8 + rr;
                int4 av = ((const int4*)(bufc + rowl * 128))[lane];
                int diagr = (i0 + rowl) - (J0 + o * 128);
                int jr = lane * 4;
                bool v0 = (av.x > 0) || (jr     == diagr);
                bool v1 = (av.y > 0) || (jr + 1 == diagr);
                bool v2 = (av.z > 0) || (jr + 2 == diagr);
                bool v3 = (av.w > 0) || (jr + 3 == diagr);
                uint32_t b0 = __ballot_sync(0xffffffffu, v0);
                uint32_t b1 = __ballot_sync(0xffffffffu, v1);
                uint32_t b2 = __ballot_sync(0xffffffffu, v2);
                uint32_t b3 = __ballot_sync(0xffffffffu, v3);
                float4 sv = *(const float4*)(s2S + o * 128 + jr);
                float m2 = -3.0e38f;
                m2 = fmaxf(m2, v0 ? sv.x : -3.0e38f);
                m2 = fmaxf(m2, v1 ? sv.y : -3.0e38f);
                m2 = fmaxf(m2, v2 ? sv.z : -3.0e38f);
                m2 = fmaxf(m2, v3 ? sv.w : -3.0e38f);
#pragma unroll
                for (int off = 16; off; off >>= 1)
                    m2 = fmaxf(m2, __shfl_xor_sync(0xffffffffu, m2, off));
                if (lane == 0) {
                    maskC[rowl][0] = b0;
                    maskC[rowl][1] = b1;
                    maskC[rowl][2] = b2;
                    maskC[rowl][3] = b3;
                    float xm = s1s[rowl] + m2;
                    xm = fmaxf(xm, 0.2f * xm);          // chunk logit max
                    float mo = msS[rowl];
                    float mn = fmaxf(mo, xm);
                    fsS[rowl] = ex2f(mo - mn);          // rescale (0 if first)
                    msS[rowl] = mn;
                }
            }
        }
        asm volatile("cp.async.wait_group 1;" ::: "memory");   // Wh o resident
        __syncthreads();

        // -- rescale accumulators by this chunk's factor --
        float fA = fsS[myrowA], fB = fsS[myrowB];
        float mAv = msS[myrowA], mBv = msS[myrowB];
        float s1A = s1s[myrowA], s1B = s1s[myrowB];
        float cA  = s1A - mAv,  c5A = 0.2f * s1A - mAv;
        float cB  = s1B - mBv,  c5B = 0.2f * s1B - mBv;
#pragma unroll
        for (int nf = 0; nf < 8; nf++) {
            acc[nf].x *= fA; acc[nf].y *= fA;
            acc[nf].z *= fB; acc[nf].w *= fB;
        }
        lA *= fA; lB *= fB;

        uint32_t mwA = maskC[myrowA][tg];
        uint32_t mwB = maskC[myrowB][tg];
        const float2* s2pg = s2pair + (o * 16 + grp * 8) * 4 + tg;
        const float*  wpg  = whsP + grp * 4352 + tg * 136 + g * 4;

#pragma unroll
        for (int kk = 0; kk < 8; kk++) {
            float2 sp = s2pg[kk * 4];
            int bit0 = grp * 16 + kk * 2, bit1 = bit0 + 1;

            float ya0 = fmaxf(sp.x + cA, fmaf(0.2f, sp.x, c5A));
            float ya1 = fmaxf(sp.y + cA, fmaf(0.2f, sp.y, c5A));
            float yb0 = fmaxf(sp.x + cB, fmaf(0.2f, sp.x, c5B));
            float yb1 = fmaxf(sp.y + cB, fmaf(0.2f, sp.y, c5B));

            ya0 = ((mwA >> bit0) & 1u) ? ya0 : -1000.f;
            ya1 = ((mwA >> bit1) & 1u) ? ya1 : -1000.f;
            yb0 = ((mwB >> bit0) & 1u) ? yb0 : -1000.f;
            yb1 = ((mwB >> bit1) & 1u) ? yb1 : -1000.f;

            // raw fp32 p; HMMA.TF32 truncates operands to tf32 in HW
            float pa0 = ex2f(ya0);
            float pa1 = ex2f(ya1);
            float pb0 = ex2f(yb0);
            float pb1 = ex2f(yb1);
            lA += pa0 + pa1;
            lB += pb0 + pb1;

            uint32_t a0 = __float_as_uint(pa0);
            uint32_t a1 = __float_as_uint(pb0);
            uint32_t a2 = __float_as_uint(pa1);
            uint32_t a3 = __float_as_uint(pb1);

            const float* wk = wpg + kk * 4 * 136;
#pragma unroll
            for (int nf = 0; nf < 4; nf++) {
                float4 wp = *(const float4*)(wk + nf * 32);
                mma_tf32((float*)&acc[nf],
                         a0, a1, a2, a3,
                         __float_as_uint(wp.x), __float_as_uint(wp.y));
                mma_tf32((float*)&acc[nf + 4],
                         a0, a1, a2, a3,
                         __float_as_uint(wp.z), __float_as_uint(wp.w));
            }
        }
    }

    asm volatile("cp.async.wait_group 0;" ::: "memory");   // drain dummy A8

    // ---- cross-group reduction (alias whsP) + partial write ----
    __syncthreads();
    if (t < 64) g_partm[bid][t] = msS[t];
    float4* accS = (float4*)whsP;
    if (grp == 1) {
#pragma unroll
        for (int nf = 0; nf < 8; nf++) accS[lt * 9 + nf] = acc[nf];
        accS[lt * 9 + 8] = make_float4(lA, lB, 0.f, 0.f);
    }
    __syncthreads();
    if (grp == 0) {
#pragma unroll
        for (int nf = 0; nf < 8; nf++) {
            float4 o = accS[lt * 9 + nf];
            acc[nf].x += o.x; acc[nf].y += o.y; acc[nf].z += o.z; acc[nf].w += o.w;
        }
        float4 lo = accS[lt * 9 + 8];
        lA += lo.x; lB += lo.y;
        lA += __shfl_xor_sync(0xffffffffu, lA, 1);
        lA += __shfl_xor_sync(0xffffffffu, lA, 2);
        lB += __shfl_xor_sync(0xffffffffu, lB, 1);
        lB += __shfl_xor_sync(0xffffffffu, lB, 2);

        int row_lo = m0 + g, row_hi = row_lo + 8;
#pragma unroll
        for (int nf = 0; nf < 8; nf++) {
            int col = (nf < 4) ? (nf * 8 + 2 * tg) : (32 + (nf - 4) * 8 + 2 * tg);
            *(float2*)&g_part[bid][row_lo][col] = make_float2(acc[nf].x, acc[nf].y);
            *(float2*)&g_part[bid][row_hi][col] = make_float2(acc[nf].z, acc[nf].w);
        }
        if (tg == 0) {
            g_part[bid][row_lo][64] = lA;
            g_part[bid][row_hi][64] = lB;
        }
    }
}

// ---------------------------------------------------------------------------
// k_comb (R16 verbatim): 512 blocks x 128 threads; all loads up front.
// ---------------------------------------------------------------------------
__global__ __launch_bounds__(128) void k_comb(float* __restrict__ out)
{
    int bid = blockIdx.x;
    int tile = bid >> 1;
    int t = threadIdx.x;
    int ri = (bid & 1) * 32 + (t >> 2);
    int cq = t & 3;
    int p0 = tile * 2, p1 = p0 + 1;

    float4 x0[4], x1[4];
#pragma unroll
    for (int q = 0; q < 4; q++) {
        int col = cq * 16 + q * 4;
        x0[q] = *(const float4*)&g_part[p0][ri][col];
        x1[q] = *(const float4*)&g_part[p1][ri][col];
    }
    float mh0 = g_partm[p0][ri], mh1 = g_partm[p1][ri];
    float l0 = g_part[p0][ri][64], l1 = g_part[p1][ri][64];

    float M = fmaxf(mh0, mh1);
    float w0 = ex2f(mh0 - M), w1 = ex2f(mh1 - M);
    float inv = 1.f / (l0 * w0 + l1 * w1);

    size_t rowbase = ((size_t)tile * 64 + ri) * FF;
#pragma unroll
    for (int q = 0; q < 4; q++) {
        int col = cq * 16 + q * 4;
        float4 v;
        v.x = fmaxf((x0[q].x * w0 + x1[q].x * w1) * inv, 0.f);
        v.y = fmaxf((x0[q].y * w0 + x1[q].y * w1) * inv, 0.f);
        v.z = fmaxf((x0[q].z * w0 + x1[q].z * w1) * inv, 0.f);
        v.w = fmaxf((x0[q].w * w0 + x1[q].w * w1) * inv, 0.f);
        *(float4*)(out + rowbase + col) = v;
    }
}

// ---------------------------------------------------------------------------
extern "C" void kernel_launch(void* const* d_in, const int* in_sizes, int n_in,
                              void* d_out, int out_size)
{
    const float* H = (const float*)d_in[0];   // (8, 2048, 128) f32
    const int*   A = (const int*)d_in[1];     // (8, 2048, 2048) i32
    const float* W = (const float*)d_in[2];   // (128, 64) f32
    const float* a = (const float*)d_in[3];   // (128,) f32
    float* out = (float*)d_out;               // (8, 2048, 64) f32

    cudaFuncSetAttribute(k_wh,  cudaFuncAttributeMaxDynamicSharedMemorySize, KWH_SMEM);
    cudaFuncSetAttribute(k_out, cudaFuncAttributeMaxDynamicSharedMemorySize, KOUT_SMEM);

    k_wh<<<NROWS / 64, 128, KWH_SMEM>>>(H, W, a);
    k_out<<<512, 256, KOUT_SMEM>>>(A);
    k_comb<<<512, 128>>>(out);
}